// round 2
// baseline (speedup 1.0000x reference)
#include <cuda_runtime.h>
#include <math.h>

// Reservoir (2-layer leaky ESN) fp32 baseline.
//   T=512, B=64, I=128, H=1024, alpha=0.5
//   out[t,b,l,h], layer0 states at l=0, layer1 at l=1.
//
// Structure:
//   Phase A : g_U0[t,b,h] = sum_i x[t,b,i] * W_in0[h,i]        (parallel GEMM)
//   Steps   : for s in 0..512: one launch doing
//               layer0 step t=s   : pre = U0[t] + h0 @ W_hat0^T          (K=1024)
//               layer1 step t=s-1 : pre = e0[t] @ W_in1^T + h1 @ W_hat1^T (K=2048)
//             Each layer-step is split-K across blocks; partials land in
//             g_part; the last-arriving block per (layer, n-tile) (threadfence
//             + counter election) sums partials, applies the leaky-tanh update
//             and writes out[t,:,l,:]. No float atomics -> bitwise deterministic.

#define TT 512
#define BB 64
#define II 128
#define HH 1024

// scratch (static __device__: no allocations anywhere, per harness rules)
static __device__ float g_U0[TT * BB * HH];          // 128 MB
static __device__ float g_part[2][16][BB * HH];      // 8 MB split-K partials
static __device__ int   g_cnt[2][8];                 // zero-init; reset by finalizer

// ---------------------------------------------------------------------------
// Phase A: U0 = x @ W_in0^T.  M=32768 (t*b), N=1024 (h), K=128.
// BM=128, BN=64, BK=16, 256 threads, 8x4 micro-tile.
// ---------------------------------------------------------------------------
__global__ __launch_bounds__(256) void u0_gemm(const float* __restrict__ x,
                                               const float* __restrict__ Win0)
{
    __shared__ float As[16][132];   // [k][m], padded: 16B-aligned rows, low conflicts
    __shared__ float Bs[16][68];    // [k][n]

    const int tid = threadIdx.x;
    const int bm0 = blockIdx.y * 128;
    const int bn0 = blockIdx.x * 64;
    const int m0  = (tid & 15) * 8;
    const int n0  = (tid >> 4) * 4;
    const int lrow = tid >> 2;        // 0..63
    const int lk   = (tid & 3) * 4;   // 0,4,8,12

    float c[8][4];
#pragma unroll
    for (int i = 0; i < 8; ++i)
#pragma unroll
        for (int j = 0; j < 4; ++j) c[i][j] = 0.f;

    for (int kt = 0; kt < 8; ++kt) {
        const int k0 = kt * 16;
#pragma unroll
        for (int it = 0; it < 2; ++it) {
            const int ar = lrow + it * 64;
            const float4 v = *(const float4*)&x[(bm0 + ar) * II + k0 + lk];
            As[lk + 0][ar] = v.x; As[lk + 1][ar] = v.y;
            As[lk + 2][ar] = v.z; As[lk + 3][ar] = v.w;
        }
        {
            const float4 v = *(const float4*)&Win0[(bn0 + lrow) * II + k0 + lk];
            Bs[lk + 0][lrow] = v.x; Bs[lk + 1][lrow] = v.y;
            Bs[lk + 2][lrow] = v.z; Bs[lk + 3][lrow] = v.w;
        }
        __syncthreads();
#pragma unroll
        for (int kk = 0; kk < 16; ++kk) {
            const float4 a0 = *(const float4*)&As[kk][m0];
            const float4 a1 = *(const float4*)&As[kk][m0 + 4];
            const float4 b  = *(const float4*)&Bs[kk][n0];
            const float av[8] = {a0.x, a0.y, a0.z, a0.w, a1.x, a1.y, a1.z, a1.w};
            const float bv[4] = {b.x, b.y, b.z, b.w};
#pragma unroll
            for (int i = 0; i < 8; ++i)
#pragma unroll
                for (int j = 0; j < 4; ++j) c[i][j] = fmaf(av[i], bv[j], c[i][j]);
        }
        __syncthreads();
    }
#pragma unroll
    for (int i = 0; i < 8; ++i) {
        const float4 v = make_float4(c[i][0], c[i][1], c[i][2], c[i][3]);
        *(float4*)&g_U0[(bm0 + m0 + i) * HH + bn0 + n0] = v;
    }
}

// ---------------------------------------------------------------------------
// One super-step s: layer0 step t=s (s<512), layer1 step t=s-1 (s>=1).
// Grid = 192 blocks:
//   bid <  64 : layer0, nt = bid&7 (128-wide h tile), ks = bid>>3 (8 x K=128)
//   bid >= 64 : layer1, nt = (bid-64)&7, ks = (bid-64)>>4? no: >>3 (16 x K=128)
// Block GEMM tile: M=64 (batch) x N=128 (h) x Kslice=128, 4x8 micro-tile.
// ---------------------------------------------------------------------------
__global__ __launch_bounds__(256) void step_kernel(const float* __restrict__ What0,
                                                   const float* __restrict__ Win1,
                                                   const float* __restrict__ What1,
                                                   float* __restrict__ out,
                                                   const int s)
{
    __shared__ float As[16][68];    // [k][b]
    __shared__ float Bs[16][132];   // [k][h_local]
    __shared__ int   isLast;

    const int bid = blockIdx.x;
    const int tid = threadIdx.x;

    int layer, nt, ks, t;
    const float* aBase = 0;   // activation rows, row stride 2048 within out
    const float* wBase = 0;   // weight rows, row stride 1024
    int azero = 0;

    if (bid < 64) {
        if (s >= TT) return;                   // layer0 done
        layer = 0; nt = bid & 7; ks = bid >> 3; t = s;
        const int kb = ks * 128;
        wBase = What0 + kb;
        if (t > 0) aBase = out + (t - 1) * BB * 2048 + kb;   // h0[t-1], layer off 0
        else       azero = 1;
    } else {
        if (s == 0) return;                    // layer1 not started
        layer = 1; const int b2 = bid - 64; nt = b2 & 7; ks = b2 >> 3; t = s - 1;
        const int kg = ks * 128;
        if (kg < HH) {                         // W_in1 segment, A = e0[t]
            wBase = Win1 + kg;
            aBase = out + t * BB * 2048 + kg;                // layer-0 states
        } else {                               // W_hat1 segment, A = h1[t-1]
            const int kb = kg - HH;
            wBase = What1 + kb;
            if (t > 0) aBase = out + (t - 1) * BB * 2048 + HH + kb;
            else       azero = 1;
        }
    }

    const int m0 = (tid & 15) * 4;     // 4 batch rows
    const int n0 = (tid >> 4) * 8;     // 8 h columns
    const int lrow = tid >> 2;         // 0..63
    const int lk   = (tid & 3) * 4;

    float c[4][8];
#pragma unroll
    for (int i = 0; i < 4; ++i)
#pragma unroll
        for (int j = 0; j < 8; ++j) c[i][j] = 0.f;

    for (int kt = 0; kt < 8; ++kt) {
        const int k0 = kt * 16;
        {
            float4 v = make_float4(0.f, 0.f, 0.f, 0.f);
            if (!azero) v = *(const float4*)&aBase[lrow * 2048 + k0 + lk];
            As[lk + 0][lrow] = v.x; As[lk + 1][lrow] = v.y;
            As[lk + 2][lrow] = v.z; As[lk + 3][lrow] = v.w;
        }
#pragma unroll
        for (int it = 0; it < 2; ++it) {
            const int br = lrow + it * 64;
            const float4 v = *(const float4*)&wBase[(nt * 128 + br) * HH + k0 + lk];
            Bs[lk + 0][br] = v.x; Bs[lk + 1][br] = v.y;
            Bs[lk + 2][br] = v.z; Bs[lk + 3][br] = v.w;
        }
        __syncthreads();
#pragma unroll
        for (int kk = 0; kk < 16; ++kk) {
            const float4 a  = *(const float4*)&As[kk][m0];
            const float4 b0 = *(const float4*)&Bs[kk][n0];
            const float4 b1 = *(const float4*)&Bs[kk][n0 + 4];
            const float av[4] = {a.x, a.y, a.z, a.w};
            const float bv[8] = {b0.x, b0.y, b0.z, b0.w, b1.x, b1.y, b1.z, b1.w};
#pragma unroll
            for (int i = 0; i < 4; ++i)
#pragma unroll
                for (int j = 0; j < 8; ++j) c[i][j] = fmaf(av[i], bv[j], c[i][j]);
        }
        __syncthreads();
    }

    // write split-K partials (disjoint h-range per nt, disjoint slab per ks)
    float* const pp = g_part[layer][ks];
#pragma unroll
    for (int i = 0; i < 4; ++i) {
        const int base = (m0 + i) * HH + nt * 128 + n0;
        *(float4*)&pp[base]     = make_float4(c[i][0], c[i][1], c[i][2], c[i][3]);
        *(float4*)&pp[base + 4] = make_float4(c[i][4], c[i][5], c[i][6], c[i][7]);
    }

    // threadfence-counter election: last block per (layer, nt) finalizes
    __threadfence();
    __syncthreads();
    const int ksplit = (layer == 0) ? 8 : 16;
    if (tid == 0) {
        const int old = atomicAdd(&g_cnt[layer][nt], 1);
        isLast = (old == ksplit - 1);
    }
    __syncthreads();
    if (!isLast) return;

    // finalize: pre = sum(partials) (+U0 for layer0); h_new = 0.5h + 0.5 tanh(pre)
    for (int e = tid; e < 64 * 128; e += 256) {
        const int b  = e >> 7;
        const int h  = nt * 128 + (e & 127);
        float pre = 0.f;
        for (int k2 = 0; k2 < ksplit; ++k2) pre += g_part[layer][k2][b * HH + h];
        if (layer == 0) pre += g_U0[(t * BB + b) * HH + h];
        float hp = 0.f;
        if (t > 0) hp = out[((t - 1) * BB + b) * 2048 + layer * HH + h];
        out[(t * BB + b) * 2048 + layer * HH + h] = 0.5f * hp + 0.5f * tanhf(pre);
    }
    if (tid == 0) g_cnt[layer][nt] = 0;   // restore invariant for next launch/replay
}

// ---------------------------------------------------------------------------
extern "C" void kernel_launch(void* const* d_in, const int* in_sizes, int n_in,
                              void* d_out, int out_size)
{
    const float* x     = (const float*)d_in[0];   // [512,64,128]
    const float* Win0  = (const float*)d_in[1];   // [1024,128]
    const float* What0 = (const float*)d_in[2];   // [1024,1024]
    const float* Win1  = (const float*)d_in[3];   // [1024,1024]
    const float* What1 = (const float*)d_in[4];   // [1024,1024]
    float* out = (float*)d_out;                   // [512,64,2,1024]

    (void)in_sizes; (void)n_in; (void)out_size;

    // Phase A: U0 = x @ W_in0^T
    dim3 gA(HH / 64, (TT * BB) / 128);            // 16 x 256 blocks
    u0_gemm<<<gA, 256>>>(x, Win0);

    // Interleaved scans: layer0 step s + layer1 step s-1 per launch
    for (int s = 0; s <= TT; ++s) {
        step_kernel<<<192, 256>>>(What0, Win1, What1, out, s);
    }
}

// round 4
// speedup vs baseline: 2.5892x; 2.5892x over previous
#include <cuda_runtime.h>
#include <math.h>

#define NBLK 128
#define NTHR 256
#define TT   512
#define BB   64
#define II   128
#define HH   1024
#define L0_NB 48
#define L0_PK 6
#define L1_PK 10
#define MAXK  208
#define SMEM_BYTES ((MAXK * 128 + MAXK * 64) * 4)   // Bs + As = 159744 B

static __device__ float g_xT[TT * II * BB];      // x transposed [t][i][b]
static __device__ float g_h0T[2][HH * BB];       // layer0 state ping-pong [h][b]
static __device__ float g_h1T[2][HH * BB];
static __device__ float g_part0[8 * L0_PK * BB * 128];
static __device__ float g_part1[8 * L1_PK * BB * 128];
static __device__ int      g_cnt[16];            // per-(layer,pn) arrive counters
static __device__ unsigned g_barcnt;             // grid barrier
static __device__ unsigned g_gen;                // monotonic generation

__device__ __forceinline__ unsigned ldacq(const unsigned* p) {
    unsigned v;
    asm volatile("ld.acquire.gpu.global.u32 %0, [%1];" : "=r"(v) : "l"(p));
    return v;
}
__device__ __forceinline__ unsigned long long pack2(float a) {
    unsigned long long r;
    asm("mov.b64 %0, {%1, %2};" : "=l"(r) : "f"(a), "f"(a));
    return r;
}
__device__ __forceinline__ void fma2(unsigned long long& d,
                                     unsigned long long a, unsigned long long b) {
    asm("fma.rn.f32x2 %0, %1, %2, %0;" : "+l"(d) : "l"(a), "l"(b));
}
__device__ __forceinline__ float4 ldcg4(const float* p) {
    return __ldcg((const float4*)p);
}
__device__ __forceinline__ void copy_seg(float* dst, const float* src, int nf, int tid) {
    for (int i = tid * 4; i < nf; i += NTHR * 4)
        *(float4*)(dst + i) = __ldcg((const float4*)(src + i));
}
__device__ __forceinline__ void zero_seg(float* dst, int nf, int tid) {
    const float4 z = make_float4(0.f, 0.f, 0.f, 0.f);
    for (int i = tid * 4; i < nf; i += NTHR * 4) *(float4*)(dst + i) = z;
}
__device__ __forceinline__ void grid_barrier(int tid) {
    __syncthreads();
    if (tid == 0) {
        unsigned g0 = ldacq(&g_gen);            // read BEFORE arriving
        __threadfence();
        unsigned old = atomicAdd(&g_barcnt, 1);
        if (old == NBLK - 1) {
            g_barcnt = 0;
            __threadfence();
            atomicAdd(&g_gen, 1);
        } else {
            while (ldacq(&g_gen) == g0) {}
        }
    }
    __syncthreads();
}

// one-time x[t][b][i] -> xT[t][i][b]
__global__ __launch_bounds__(256) void transpose_x(const float* __restrict__ x) {
    __shared__ float ts[64][129];
    const int t = blockIdx.x, tid = threadIdx.x;
    for (int idx = tid; idx < 64 * 128; idx += 256)
        ts[idx >> 7][idx & 127] = x[(t * 64 + (idx >> 7)) * 128 + (idx & 127)];
    __syncthreads();
    for (int idx = tid; idx < 64 * 128; idx += 256) {
        const int i = idx >> 6, b = idx & 63;
        g_xT[(t * 128 + i) * 64 + b] = ts[b][i];
    }
}

__global__ __launch_bounds__(NTHR, 1) void esn_kernel(const float* __restrict__ Win0,
                                                      const float* __restrict__ What0,
                                                      const float* __restrict__ Win1,
                                                      const float* __restrict__ What1,
                                                      float* __restrict__ out)
{
    extern __shared__ float smem[];
    float* const Bs = smem;                 // [klen][128] weights k-major
    float* const As = smem + MAXK * 128;    // [klen][64] activations k-major

    const int tid = threadIdx.x;
    const int bid = blockIdx.x;

    int layer, pn, pk, kbase, klen, Pk;
    if (bid < L0_NB) {
        layer = 0; pn = bid / L0_PK; pk = bid % L0_PK;
        kbase = pk * 192; klen = 192; Pk = L0_PK;     // K=1152: x(128)|h0(1024)
    } else {
        const int b2 = bid - L0_NB;
        layer = 1; pn = b2 / L1_PK; pk = b2 % L1_PK; Pk = L1_PK;
        if (pk < 8)       { kbase = pk * 208; klen = 208; }   // K=2048: e0|h1
        else if (pk == 8) { kbase = 1664;     klen = 192; }
        else              { kbase = 1856;     klen = 192; }
    }
    const int row0 = pn * 128;
    const int grp  = layer * 8 + pn;

    // ---- prologue: stage weight slice (once) ----
    {
        const float* WI = (layer == 0) ? Win0 : Win1;
        const float* WH = (layer == 0) ? What0 : What1;
        const int istride = (layer == 0) ? II : HH;
        const int bound   = (layer == 0) ? II : HH;
        for (int n = tid >> 5; n < 128; n += 8) {
            const float* rowIn  = WI + (row0 + n) * istride;
            const float* rowHat = WH + (row0 + n) * HH;
            for (int k = (tid & 31) * 4; k < klen; k += 128) {
                const int kg = kbase + k;
                const float4 w = (kg < bound) ? *(const float4*)(rowIn + kg)
                                              : *(const float4*)(rowHat + kg - bound);
                Bs[(k + 0) * 128 + n] = w.x; Bs[(k + 1) * 128 + n] = w.y;
                Bs[(k + 2) * 128 + n] = w.z; Bs[(k + 3) * 128 + n] = w.w;
            }
        }
    }

    float* const myPart = (layer == 0) ? &g_part0[(pn * L0_PK + pk) * BB * 128]
                                       : &g_part1[(pn * L1_PK + pk) * BB * 128];
    const float* const partBase = (layer == 0) ? &g_part0[pn * L0_PK * BB * 128]
                                               : &g_part1[pn * L1_PK * BB * 128];
    const int m0 = (tid & 15) * 4;
    const int n0 = (tid >> 4) * 8;
    int myIter = 0;

    for (int s = 0; s <= TT; ++s) {
        const bool active = (layer == 0) ? (s < TT) : (s >= 1);
        if (active) {
            const int t = (layer == 0) ? s : s - 1;

            // ---- stage A slice [klen][64] ----
            if (layer == 0) {
                int xlen = (kbase < II) ? II - kbase : 0;      // only pk==0
                if (xlen > klen) xlen = klen;
                if (xlen > 0)
                    copy_seg(As, g_xT + (t * II + kbase) * 64, xlen * 64, tid);
                const int hlen = klen - xlen;
                if (hlen > 0) {
                    const int hstart = kbase + xlen - II;
                    if (s == 0) zero_seg(As + xlen * 64, hlen * 64, tid);
                    else copy_seg(As + xlen * 64,
                                  &g_h0T[(s - 1) & 1][hstart * 64], hlen * 64, tid);
                }
            } else {
                const int kend = kbase + klen;
                int alen = (kend < HH ? kend : HH) - kbase;
                if (alen < 0) alen = 0;
                if (alen > 0)
                    copy_seg(As, &g_h0T[(s - 1) & 1][kbase * 64], alen * 64, tid);
                const int blen = klen - alen;
                if (blen > 0) {
                    const int bstart = (kbase > HH ? kbase : HH) - HH;
                    if (s == 1) zero_seg(As + alen * 64, blen * 64, tid);
                    else copy_seg(As + alen * 64,
                                  &g_h1T[s & 1][bstart * 64], blen * 64, tid);
                }
            }
            __syncthreads();

            // ---- GEMM 64x128 x klen: 4b x 8n per thread, packed f32x2 ----
            unsigned long long acc[4][4];
#pragma unroll
            for (int i = 0; i < 4; ++i)
#pragma unroll
                for (int j = 0; j < 4; ++j) acc[i][j] = 0ULL;
            const float* Ap = As + m0;
            const float* Bp = Bs + n0;
#pragma unroll 2
            for (int k = 0; k < klen; ++k) {
                const float4 av = *(const float4*)(Ap + k * 64);
                const ulonglong2 b01 = *(const ulonglong2*)(Bp + k * 128);
                const ulonglong2 b23 = *(const ulonglong2*)(Bp + k * 128 + 4);
                const unsigned long long a0 = pack2(av.x), a1 = pack2(av.y);
                const unsigned long long a2 = pack2(av.z), a3 = pack2(av.w);
                fma2(acc[0][0], a0, b01.x); fma2(acc[0][1], a0, b01.y);
                fma2(acc[0][2], a0, b23.x); fma2(acc[0][3], a0, b23.y);
                fma2(acc[1][0], a1, b01.x); fma2(acc[1][1], a1, b01.y);
                fma2(acc[1][2], a1, b23.x); fma2(acc[1][3], a1, b23.y);
                fma2(acc[2][0], a2, b01.x); fma2(acc[2][1], a2, b01.y);
                fma2(acc[2][2], a2, b23.x); fma2(acc[2][3], a2, b23.y);
                fma2(acc[3][0], a3, b01.x); fma2(acc[3][1], a3, b01.y);
                fma2(acc[3][2], a3, b23.x); fma2(acc[3][3], a3, b23.y);
            }
#pragma unroll
            for (int i = 0; i < 4; ++i) {
                ulonglong2 v0; v0.x = acc[i][0]; v0.y = acc[i][1];
                ulonglong2 v1; v1.x = acc[i][2]; v1.y = acc[i][3];
                *(ulonglong2*)(myPart + (m0 + i) * 128 + n0)     = v0;
                *(ulonglong2*)(myPart + (m0 + i) * 128 + n0 + 4) = v1;
            }

            // ---- group arrive + spin (all Pk blocks finalize 1/Pk each) ----
            __threadfence();
            __syncthreads();
            ++myIter;
            if (tid == 0) {
                atomicAdd(&g_cnt[grp], 1);
                const unsigned tgt = (unsigned)(myIter * Pk);
                while (ldacq((const unsigned*)&g_cnt[grp]) < tgt) {}
            }
            __syncthreads();

            // ---- finalize my slice: sum partials, leaky tanh, write out+hT ----
            float* const hT = (layer == 0) ? &g_h0T[s & 1][0]
                                           : &g_h1T[(s & 1) ^ 1][0];
            const int eS = (pk * 2048) / Pk, eE = ((pk + 1) * 2048) / Pk;
            for (int e = eS + tid; e < eE; e += NTHR) {
                const int b = e >> 5;
                const int n = (e & 31) * 4;
                const float* pp = partBase + b * 128 + n;
                float4 a = ldcg4(pp);
                for (int q = 1; q < Pk; ++q) {
                    const float4 v = ldcg4(pp + q * BB * 128);
                    a.x += v.x; a.y += v.y; a.z += v.z; a.w += v.w;
                }
                float4 hp = make_float4(0.f, 0.f, 0.f, 0.f);
                if (t > 0)
                    hp = ldcg4(&out[((t - 1) * BB + b) * 2048 + layer * HH + row0 + n]);
                float4 hn;
                hn.x = 0.5f * hp.x + 0.5f * tanhf(a.x);
                hn.y = 0.5f * hp.y + 0.5f * tanhf(a.y);
                hn.z = 0.5f * hp.z + 0.5f * tanhf(a.z);
                hn.w = 0.5f * hp.w + 0.5f * tanhf(a.w);
                *(float4*)&out[(t * BB + b) * 2048 + layer * HH + row0 + n] = hn;
                hT[(row0 + n + 0) * 64 + b] = hn.x;
                hT[(row0 + n + 1) * 64 + b] = hn.y;
                hT[(row0 + n + 2) * 64 + b] = hn.z;
                hT[(row0 + n + 3) * 64 + b] = hn.w;
            }
        }
        grid_barrier(tid);
    }

    // reset group counters for next graph replay (all blocks past final barrier)
    if (bid == 0 && tid < 16) g_cnt[tid] = 0;
}

extern "C" void kernel_launch(void* const* d_in, const int* in_sizes, int n_in,
                              void* d_out, int out_size)
{
    const float* x     = (const float*)d_in[0];
    const float* Win0  = (const float*)d_in[1];
    const float* What0 = (const float*)d_in[2];
    const float* Win1  = (const float*)d_in[3];
    const float* What1 = (const float*)d_in[4];
    float* out = (float*)d_out;
    (void)in_sizes; (void)n_in; (void)out_size;

    transpose_x<<<TT, 256>>>(x);
    cudaFuncSetAttribute(esn_kernel,
                         cudaFuncAttributeMaxDynamicSharedMemorySize, SMEM_BYTES);
    esn_kernel<<<NBLK, NTHR, SMEM_BYTES>>>(Win0, What0, Win1, What1, out);
}

// round 6
// speedup vs baseline: 2.6615x; 1.0279x over previous
#include <cuda_runtime.h>
#include <math.h>

#define NBLK 128
#define NTHR 256
#define TT   512
#define BB   64
#define II   128
#define HH   1024
#define L0_NB 48
#define L0_PK 6
#define L1_PK 10
#define MAXK  208
#define SMEM_BYTES ((MAXK * 128 + MAXK * 64) * 4)   // Bs + As = 159744 B

static __device__ float g_xT[TT * II * BB];          // x transposed [t][i][b]
static __device__ float g_h0T[2][HH * BB];           // state ping-pong [h][b]
static __device__ float g_h1T[2][HH * BB];
static __device__ float g_part0[8 * L0_PK * BB * 128];
static __device__ float g_part1[8 * L1_PK * BB * 128];
static __device__ int      g_cnt[16];
static __device__ unsigned g_barcnt;
static __device__ unsigned g_gen;

__device__ __forceinline__ unsigned ldacq(const unsigned* p) {
    unsigned v;
    asm volatile("ld.acquire.gpu.global.u32 %0, [%1];" : "=r"(v) : "l"(p));
    return v;
}
__device__ __forceinline__ unsigned long long pack2(float a) {
    unsigned long long r;
    asm("mov.b64 %0, {%1, %2};" : "=l"(r) : "f"(a), "f"(a));
    return r;
}
__device__ __forceinline__ void fma2(unsigned long long& d,
                                     unsigned long long a, unsigned long long b) {
    asm("fma.rn.f32x2 %0, %1, %2, %0;" : "+l"(d) : "l"(a), "l"(b));
}
__device__ __forceinline__ float4 ldcg4(const float* p) {
    return __ldcg((const float4*)p);
}
__device__ __forceinline__ void cpasync16(unsigned s, const float* g) {
    asm volatile("cp.async.cg.shared.global [%0], [%1], 16;" :: "r"(s), "l"(g));
}
__device__ __forceinline__ void cpcommit() {
    asm volatile("cp.async.commit_group;");
}
template <int N>
__device__ __forceinline__ void cpwait() {
    asm volatile("cp.async.wait_group %0;" :: "n"(N));
}
__device__ __forceinline__ float ftanh(float x) {
    const float e = __expf(2.0f * x);
    return 1.0f - __fdividef(2.0f, e + 1.0f);
}
__device__ __forceinline__ void copy_seg(float* dst, const float* src, int nf, int tid) {
    for (int i = tid * 4; i < nf; i += NTHR * 4)
        *(float4*)(dst + i) = __ldcg((const float4*)(src + i));
}
__device__ __forceinline__ void zero_seg(float* dst, int nf, int tid) {
    const float4 z = make_float4(0.f, 0.f, 0.f, 0.f);
    for (int i = tid * 4; i < nf; i += NTHR * 4) *(float4*)(dst + i) = z;
}
__device__ __forceinline__ void grid_barrier(int tid) {
    __syncthreads();
    if (tid == 0) {
        unsigned g0 = ldacq(&g_gen);          // read BEFORE arriving
        __threadfence();
        unsigned old = atomicAdd(&g_barcnt, 1);
        if (old == NBLK - 1) {
            g_barcnt = 0;
            __threadfence();
            atomicAdd(&g_gen, 1);
        } else {
            while (ldacq(&g_gen) == g0) {}
        }
    }
    __syncthreads();
}

template <int PK>
__device__ __forceinline__ void finalize_slice(const float* __restrict__ partBase,
                                               float* __restrict__ out,
                                               float* __restrict__ hT,
                                               int t, int layer, int row0,
                                               int pk, int tid)
{
    const int eS = (pk * 2048) / PK, eE = ((pk + 1) * 2048) / PK;
    for (int e = eS + tid; e < eE; e += NTHR) {
        const int b = e >> 5;
        const int n = (e & 31) * 4;
        const float* pp = partBase + b * 128 + n;
        float4 a = ldcg4(pp);
#pragma unroll
        for (int q = 1; q < PK; ++q) {
            const float4 v = ldcg4(pp + q * BB * 128);
            a.x += v.x; a.y += v.y; a.z += v.z; a.w += v.w;
        }
        float4 hp = make_float4(0.f, 0.f, 0.f, 0.f);
        if (t > 0)
            hp = ldcg4(&out[((t - 1) * BB + b) * 2048 + layer * HH + row0 + n]);
        float4 hn;
        hn.x = 0.5f * hp.x + 0.5f * ftanh(a.x);
        hn.y = 0.5f * hp.y + 0.5f * ftanh(a.y);
        hn.z = 0.5f * hp.z + 0.5f * ftanh(a.z);
        hn.w = 0.5f * hp.w + 0.5f * ftanh(a.w);
        *(float4*)&out[(t * BB + b) * 2048 + layer * HH + row0 + n] = hn;
        hT[(row0 + n + 0) * 64 + b] = hn.x;
        hT[(row0 + n + 1) * 64 + b] = hn.y;
        hT[(row0 + n + 2) * 64 + b] = hn.z;
        hT[(row0 + n + 3) * 64 + b] = hn.w;
    }
}

__global__ __launch_bounds__(256) void transpose_x(const float* __restrict__ x) {
    __shared__ float ts[64][129];
    const int t = blockIdx.x, tid = threadIdx.x;
    for (int idx = tid; idx < 64 * 128; idx += 256)
        ts[idx >> 7][idx & 127] = x[(t * 64 + (idx >> 7)) * 128 + (idx & 127)];
    __syncthreads();
    for (int idx = tid; idx < 64 * 128; idx += 256) {
        const int i = idx >> 6, b = idx & 63;
        g_xT[(t * 128 + i) * 64 + b] = ts[b][i];
    }
}

__global__ __launch_bounds__(NTHR, 1) void esn_kernel(const float* __restrict__ Win0,
                                                      const float* __restrict__ What0,
                                                      const float* __restrict__ Win1,
                                                      const float* __restrict__ What1,
                                                      float* __restrict__ out)
{
    extern __shared__ float smem[];
    float* const Bs = smem;                 // [klen][128] weights k-major
    float* const As = smem + MAXK * 128;    // [klen][64] activations k-major
    const unsigned sAs = (unsigned)__cvta_generic_to_shared(As);

    const int tid = threadIdx.x;
    const int bid = blockIdx.x;

    int layer, pn, pk, kbase, klen, Pk;
    if (bid < L0_NB) {
        layer = 0; pn = bid / L0_PK; pk = bid % L0_PK;
        kbase = pk * 192; klen = 192; Pk = L0_PK;           // K=1152: x|h0
    } else {
        const int b2 = bid - L0_NB;
        layer = 1; pn = b2 / L1_PK; pk = b2 % L1_PK; Pk = L1_PK;
        if (pk < 8)       { kbase = pk * 208; klen = 208; } // K=2048: e0|h1
        else if (pk == 8) { kbase = 1664;     klen = 192; }
        else              { kbase = 1856;     klen = 192; }
    }
    const int row0 = pn * 128;
    const int grp  = layer * 8 + pn;
    const int ck   = klen >> 2;             // chunk rows (52 or 48)
    const int bound = (layer == 0) ? II : HH;

    // ---- stage weight slice once ----
    {
        const float* WI = (layer == 0) ? Win0 : Win1;
        const float* WH = (layer == 0) ? What0 : What1;
        for (int n = tid >> 5; n < 128; n += 8) {
            const float* rowIn  = WI + (row0 + n) * bound;
            const float* rowHat = WH + (row0 + n) * HH;
            for (int k = (tid & 31) * 4; k < klen; k += 128) {
                const int kg = kbase + k;
                const float4 w = (kg < bound) ? *(const float4*)(rowIn + kg)
                                              : *(const float4*)(rowHat + kg - bound);
                Bs[(k + 0) * 128 + n] = w.x; Bs[(k + 1) * 128 + n] = w.y;
                Bs[(k + 2) * 128 + n] = w.z; Bs[(k + 3) * 128 + n] = w.w;
            }
        }
    }

    float* const myPart = (layer == 0) ? &g_part0[(pn * L0_PK + pk) * BB * 128]
                                       : &g_part1[(pn * L1_PK + pk) * BB * 128];
    const float* const partBase = (layer == 0) ? &g_part0[pn * L0_PK * BB * 128]
                                               : &g_part1[pn * L1_PK * BB * 128];
    const int m0 = (tid & 15) * 4;
    const int n0 = (tid >> 4) * 8;
    int myIter = 0;

    for (int s = 0; s <= TT; ++s) {
        const bool active = (layer == 0) ? (s < TT) : (s >= 1);
        if (active) {
            const int t = (layer == 0) ? s : s - 1;

            // ---- A segments (row units of 64 floats) ----
            const float* src0;
            const float* src1 = 0;
            int len0, len1;
            bool zerotail;
            if (layer == 0) {
                len0 = II - kbase; if (len0 < 0) len0 = 0; if (len0 > klen) len0 = klen;
                len1 = klen - len0;
                src0 = g_xT + (t * II + kbase) * 64;
                if (len1 > 0) src1 = &g_h0T[(s - 1) & 1][(kbase + len0 - II) * 64];
                zerotail = (s == 0) && (len1 > 0);
            } else {
                len0 = HH - kbase; if (len0 < 0) len0 = 0; if (len0 > klen) len0 = klen;
                len1 = klen - len0;
                src0 = &g_h0T[(s - 1) & 1][kbase * 64];
                if (len1 > 0) src1 = &g_h1T[s & 1][(kbase + len0 - HH) * 64];
                zerotail = (s == 1) && (len1 > 0);
            }
            const bool useAsync = !zerotail;

            if (useAsync) {
                // 4 async chunks, one commit group each (overlap with GEMM below)
#pragma unroll
                for (int c = 0; c < 4; ++c) {
                    const int r0c = c * ck;
                    const int nops = ck * 16;
                    for (int i = tid; i < nops; i += NTHR) {
                        const int r = r0c + (i >> 4);
                        const int o = (i & 15) * 4;
                        const float* src = (r < len0) ? src0 + r * 64 + o
                                                      : src1 + (r - len0) * 64 + o;
                        cpasync16(sAs + (unsigned)(r * 64 + o) * 4u, src);
                    }
                    cpcommit();
                }
            } else {
                if (len0 > 0) copy_seg(As, src0, len0 * 64, tid);
                if (len1 > 0) zero_seg(As + len0 * 64, len1 * 64, tid);
                __syncthreads();
            }

            // ---- GEMM 64x128 over klen, chunked; 4b x 8n, packed f32x2 ----
            unsigned long long acc[4][4];
#pragma unroll
            for (int i = 0; i < 4; ++i)
#pragma unroll
                for (int j = 0; j < 4; ++j) acc[i][j] = 0ULL;
            const float* Ap = As + m0;
            const float* Bp = Bs + n0;
#pragma unroll
            for (int c = 0; c < 4; ++c) {
                if (useAsync) {
                    if (c == 0) cpwait<3>();
                    else if (c == 1) cpwait<2>();
                    else if (c == 2) cpwait<1>();
                    else cpwait<0>();
                    __syncthreads();
                }
                const int kE = (c + 1) * ck;
#pragma unroll 4
                for (int k = c * ck; k < kE; ++k) {
                    const float4 av = *(const float4*)(Ap + k * 64);
                    const ulonglong2 b01 = *(const ulonglong2*)(Bp + k * 128);
                    const ulonglong2 b23 = *(const ulonglong2*)(Bp + k * 128 + 4);
                    const unsigned long long a0 = pack2(av.x), a1 = pack2(av.y);
                    const unsigned long long a2 = pack2(av.z), a3 = pack2(av.w);
                    fma2(acc[0][0], a0, b01.x); fma2(acc[0][1], a0, b01.y);
                    fma2(acc[0][2], a0, b23.x); fma2(acc[0][3], a0, b23.y);
                    fma2(acc[1][0], a1, b01.x); fma2(acc[1][1], a1, b01.y);
                    fma2(acc[1][2], a1, b23.x); fma2(acc[1][3], a1, b23.y);
                    fma2(acc[2][0], a2, b01.x); fma2(acc[2][1], a2, b01.y);
                    fma2(acc[2][2], a2, b23.x); fma2(acc[2][3], a2, b23.y);
                    fma2(acc[3][0], a3, b01.x); fma2(acc[3][1], a3, b01.y);
                    fma2(acc[3][2], a3, b23.x); fma2(acc[3][3], a3, b23.y);
                }
            }
#pragma unroll
            for (int i = 0; i < 4; ++i) {
                ulonglong2 v0; v0.x = acc[i][0]; v0.y = acc[i][1];
                ulonglong2 v1; v1.x = acc[i][2]; v1.y = acc[i][3];
                *(ulonglong2*)(myPart + (m0 + i) * 128 + n0)     = v0;
                *(ulonglong2*)(myPart + (m0 + i) * 128 + n0 + 4) = v1;
            }

            // ---- group arrive + spin (all Pk blocks finalize 1/Pk each) ----
            __threadfence();
            __syncthreads();
            ++myIter;
            if (tid == 0) {
                atomicAdd(&g_cnt[grp], 1);
                const unsigned tgt = (unsigned)(myIter * Pk);
                while (ldacq((const unsigned*)&g_cnt[grp]) < tgt) {}
            }
            __syncthreads();

            // ---- finalize my 1/Pk slice ----
            float* const hT = (layer == 0) ? &g_h0T[s & 1][0]
                                           : &g_h1T[(s & 1) ^ 1][0];
            if (layer == 0)
                finalize_slice<L0_PK>(partBase, out, hT, t, 0, row0, pk, tid);
            else
                finalize_slice<L1_PK>(partBase, out, hT, t, 1, row0, pk, tid);
        }
        grid_barrier(tid);
    }

    if (bid == 0 && tid < 16) g_cnt[tid] = 0;   // replay-safe reset
}

extern "C" void kernel_launch(void* const* d_in, const int* in_sizes, int n_in,
                              void* d_out, int out_size)
{
    const float* x     = (const float*)d_in[0];
    const float* Win0  = (const float*)d_in[1];
    const float* What0 = (const float*)d_in[2];
    const float* Win1  = (const float*)d_in[3];
    const float* What1 = (const float*)d_in[4];
    float* out = (float*)d_out;
    (void)in_sizes; (void)n_in; (void)out_size;

    transpose_x<<<TT, 256>>>(x);
    cudaFuncSetAttribute(esn_kernel,
                         cudaFuncAttributeMaxDynamicSharedMemorySize, SMEM_BYTES);
    esn_kernel<<<NBLK, NTHR, SMEM_BYTES>>>(Win0, What0, Win1, What1, out);
}

// round 9
// speedup vs baseline: 2.6926x; 1.0117x over previous
#include <cuda_runtime.h>
#include <math.h>

#define NBLK 128
#define NTHR 256
#define TT   512
#define BB   64
#define II   128
#define HH   1024
#define L0_NB 48
#define L0_PK 6
#define L1_PK 10
#define MAXK  208
#define SMEM_BYTES ((MAXK * 128 + MAXK * 64) * 4)   // Bs + As = 159744 B

static __device__ float g_xT[TT * II * BB];          // x transposed [t][i][b]
static __device__ float g_h0T[2][HH * BB];           // state ping-pong [h][b]
static __device__ float g_h1T[2][HH * BB];
static __device__ float g_part0[8 * L0_PK * BB * 128];
static __device__ float g_part1[8 * L1_PK * BB * 128];

// R5-proven sync state, but each counter on its OWN 128B L2 line.
struct __align__(128) PadCtr { unsigned v; unsigned pad[31]; };
static __device__ PadCtr g_grp[16];      // per-(layer,pn) monotonic arrivals
static __device__ PadCtr g_barcnt;       // barrier arrive count (reset per epoch)
static __device__ PadCtr g_gen;          // monotonic generation

__device__ __forceinline__ unsigned ldacq(const unsigned* p) {
    unsigned v;
    asm volatile("ld.acquire.gpu.global.u32 %0, [%1];" : "=r"(v) : "l"(p));
    return v;
}
__device__ __forceinline__ unsigned long long pack2(float a) {
    unsigned long long r;
    asm("mov.b64 %0, {%1, %2};" : "=l"(r) : "f"(a), "f"(a));
    return r;
}
__device__ __forceinline__ void fma2(unsigned long long& d,
                                     unsigned long long a, unsigned long long b) {
    asm("fma.rn.f32x2 %0, %1, %2, %0;" : "+l"(d) : "l"(a), "l"(b));
}
__device__ __forceinline__ float4 ldcg4(const float* p) {
    return __ldcg((const float4*)p);
}
__device__ __forceinline__ void cpasync16(unsigned s, const float* g) {
    asm volatile("cp.async.cg.shared.global [%0], [%1], 16;" :: "r"(s), "l"(g));
}
__device__ __forceinline__ void cpcommit() {
    asm volatile("cp.async.commit_group;");
}
template <int N>
__device__ __forceinline__ void cpwait() {
    asm volatile("cp.async.wait_group %0;" :: "n"(N));
}
__device__ __forceinline__ float ftanh(float x) {
    const float e = __expf(2.0f * x);
    return 1.0f - __fdividef(2.0f, e + 1.0f);
}
__device__ __forceinline__ void copy_seg(float* dst, const float* src, int nf, int tid) {
    for (int i = tid * 4; i < nf; i += NTHR * 4)
        *(float4*)(dst + i) = __ldcg((const float4*)(src + i));
}
__device__ __forceinline__ void zero_seg(float* dst, int nf, int tid) {
    const float4 z = make_float4(0.f, 0.f, 0.f, 0.f);
    for (int i = tid * 4; i < nf; i += NTHR * 4) *(float4*)(dst + i) = z;
}

// R5-proven barrier: last arriver resets count and bumps monotonic generation.
// (Identical control flow to the kernel that passed at 8932us; only the two
//  counters now live on separate 128B lines.)
__device__ __forceinline__ void grid_barrier(int tid) {
    __syncthreads();
    if (tid == 0) {
        unsigned g0 = ldacq(&g_gen.v);          // read BEFORE arriving
        __threadfence();
        unsigned old = atomicAdd(&g_barcnt.v, 1);
        if (old == NBLK - 1) {
            g_barcnt.v = 0;
            __threadfence();
            atomicAdd(&g_gen.v, 1);
        } else {
            while (ldacq(&g_gen.v) == g0) {}
        }
    }
    __syncthreads();
}

template <int PK>
__device__ __forceinline__ void finalize_slice(const float* __restrict__ partBase,
                                               float* __restrict__ out,
                                               float* __restrict__ hT,
                                               int t, int layer, int row0,
                                               int pk, int tid)
{
    const int eS = (pk * 2048) / PK, eE = ((pk + 1) * 2048) / PK;
    for (int e = eS + tid; e < eE; e += NTHR) {
        const int b = e >> 5;
        const int n = (e & 31) * 4;
        const float* pp = partBase + b * 128 + n;
        float4 a = ldcg4(pp);
#pragma unroll
        for (int q = 1; q < PK; ++q) {
            const float4 v = ldcg4(pp + q * BB * 128);
            a.x += v.x; a.y += v.y; a.z += v.z; a.w += v.w;
        }
        float4 hp = make_float4(0.f, 0.f, 0.f, 0.f);
        if (t > 0)
            hp = ldcg4(&out[((t - 1) * BB + b) * 2048 + layer * HH + row0 + n]);
        float4 hn;
        hn.x = 0.5f * hp.x + 0.5f * ftanh(a.x);
        hn.y = 0.5f * hp.y + 0.5f * ftanh(a.y);
        hn.z = 0.5f * hp.z + 0.5f * ftanh(a.z);
        hn.w = 0.5f * hp.w + 0.5f * ftanh(a.w);
        *(float4*)&out[(t * BB + b) * 2048 + layer * HH + row0 + n] = hn;
        hT[(row0 + n + 0) * 64 + b] = hn.x;
        hT[(row0 + n + 1) * 64 + b] = hn.y;
        hT[(row0 + n + 2) * 64 + b] = hn.z;
        hT[(row0 + n + 3) * 64 + b] = hn.w;
    }
}

__global__ __launch_bounds__(256) void transpose_x(const float* __restrict__ x) {
    __shared__ float ts[64][129];
    const int t = blockIdx.x, tid = threadIdx.x;
    for (int idx = tid; idx < 64 * 128; idx += 256)
        ts[idx >> 7][idx & 127] = x[(t * 64 + (idx >> 7)) * 128 + (idx & 127)];
    __syncthreads();
    for (int idx = tid; idx < 64 * 128; idx += 256) {
        const int i = idx >> 6, b = idx & 63;
        g_xT[(t * 128 + i) * 64 + b] = ts[b][i];
    }
}

__global__ __launch_bounds__(NTHR, 1) void esn_kernel(const float* __restrict__ Win0,
                                                      const float* __restrict__ What0,
                                                      const float* __restrict__ Win1,
                                                      const float* __restrict__ What1,
                                                      float* __restrict__ out)
{
    extern __shared__ float smem[];
    float* const Bs = smem;                 // [klen][128] weights k-major
    float* const As = smem + MAXK * 128;    // [klen][64] activations k-major
    const unsigned sAs = (unsigned)__cvta_generic_to_shared(As);

    const int tid = threadIdx.x;
    const int bid = blockIdx.x;

    int layer, pn, pk, kbase, klen, Pk;
    if (bid < L0_NB) {
        layer = 0; pn = bid / L0_PK; pk = bid % L0_PK;
        kbase = pk * 192; klen = 192; Pk = L0_PK;           // K=1152: x|h0
    } else {
        const int b2 = bid - L0_NB;
        layer = 1; pn = b2 / L1_PK; pk = b2 % L1_PK; Pk = L1_PK;
        if (pk < 8)       { kbase = pk * 208; klen = 208; } // K=2048: e0|h1
        else if (pk == 8) { kbase = 1664;     klen = 192; }
        else              { kbase = 1856;     klen = 192; }
    }
    const int row0 = pn * 128;
    const int grp  = layer * 8 + pn;
    const int ck   = klen >> 2;             // chunk rows (52 or 48)
    const int bound = (layer == 0) ? II : HH;

    // ---- stage weight slice once ----
    {
        const float* WI = (layer == 0) ? Win0 : Win1;
        const float* WH = (layer == 0) ? What0 : What1;
        for (int n = tid >> 5; n < 128; n += 8) {
            const float* rowIn  = WI + (row0 + n) * bound;
            const float* rowHat = WH + (row0 + n) * HH;
            for (int k = (tid & 31) * 4; k < klen; k += 128) {
                const int kg = kbase + k;
                const float4 w = (kg < bound) ? *(const float4*)(rowIn + kg)
                                              : *(const float4*)(rowHat + kg - bound);
                Bs[(k + 0) * 128 + n] = w.x; Bs[(k + 1) * 128 + n] = w.y;
                Bs[(k + 2) * 128 + n] = w.z; Bs[(k + 3) * 128 + n] = w.w;
            }
        }
    }

    float* const myPart = (layer == 0) ? &g_part0[(pn * L0_PK + pk) * BB * 128]
                                       : &g_part1[(pn * L1_PK + pk) * BB * 128];
    const float* const partBase = (layer == 0) ? &g_part0[pn * L0_PK * BB * 128]
                                               : &g_part1[pn * L1_PK * BB * 128];
    const int m0 = (tid & 15) * 4;
    const int n0 = (tid >> 4) * 8;
    int myIter = 0;

    for (int s = 0; s <= TT; ++s) {
        const bool active = (layer == 0) ? (s < TT) : (s >= 1);
        if (active) {
            const int t = (layer == 0) ? s : s - 1;

            // ---- A segments (row units of 64 floats) ----
            const float* src0;
            const float* src1 = 0;
            int len0, len1;
            bool zerotail;
            if (layer == 0) {
                len0 = II - kbase; if (len0 < 0) len0 = 0; if (len0 > klen) len0 = klen;
                len1 = klen - len0;
                src0 = g_xT + (t * II + kbase) * 64;
                if (len1 > 0) src1 = &g_h0T[(s - 1) & 1][(kbase + len0 - II) * 64];
                zerotail = (s == 0) && (len1 > 0);
            } else {
                len0 = HH - kbase; if (len0 < 0) len0 = 0; if (len0 > klen) len0 = klen;
                len1 = klen - len0;
                src0 = &g_h0T[(s - 1) & 1][kbase * 64];
                if (len1 > 0) src1 = &g_h1T[s & 1][(kbase + len0 - HH) * 64];
                zerotail = (s == 1) && (len1 > 0);
            }
            const bool useAsync = !zerotail;

            if (useAsync) {
                // 4 async chunks, one commit group each (overlap with GEMM below)
#pragma unroll
                for (int c = 0; c < 4; ++c) {
                    const int r0c = c * ck;
                    const int nops = ck * 16;
                    for (int i = tid; i < nops; i += NTHR) {
                        const int r = r0c + (i >> 4);
                        const int o = (i & 15) * 4;
                        const float* src = (r < len0) ? src0 + r * 64 + o
                                                      : src1 + (r - len0) * 64 + o;
                        cpasync16(sAs + (unsigned)(r * 64 + o) * 4u, src);
                    }
                    cpcommit();
                }
            } else {
                if (len0 > 0) copy_seg(As, src0, len0 * 64, tid);
                if (len1 > 0) zero_seg(As + len0 * 64, len1 * 64, tid);
                __syncthreads();
            }

            // ---- GEMM 64x128 over klen, chunked; 4b x 8n, packed f32x2 ----
            unsigned long long acc[4][4];
#pragma unroll
            for (int i = 0; i < 4; ++i)
#pragma unroll
                for (int j = 0; j < 4; ++j) acc[i][j] = 0ULL;
            const float* Ap = As + m0;
            const float* Bp = Bs + n0;
#pragma unroll
            for (int c = 0; c < 4; ++c) {
                if (useAsync) {
                    if (c == 0) cpwait<3>();
                    else if (c == 1) cpwait<2>();
                    else if (c == 2) cpwait<1>();
                    else cpwait<0>();
                    __syncthreads();
                }
                const int kE = (c + 1) * ck;
#pragma unroll 4
                for (int k = c * ck; k < kE; ++k) {
                    const float4 av = *(const float4*)(Ap + k * 64);
                    const ulonglong2 b01 = *(const ulonglong2*)(Bp + k * 128);
                    const ulonglong2 b23 = *(const ulonglong2*)(Bp + k * 128 + 4);
                    const unsigned long long a0 = pack2(av.x), a1 = pack2(av.y);
                    const unsigned long long a2 = pack2(av.z), a3 = pack2(av.w);
                    fma2(acc[0][0], a0, b01.x); fma2(acc[0][1], a0, b01.y);
                    fma2(acc[0][2], a0, b23.x); fma2(acc[0][3], a0, b23.y);
                    fma2(acc[1][0], a1, b01.x); fma2(acc[1][1], a1, b01.y);
                    fma2(acc[1][2], a1, b23.x); fma2(acc[1][3], a1, b23.y);
                    fma2(acc[2][0], a2, b01.x); fma2(acc[2][1], a2, b01.y);
                    fma2(acc[2][2], a2, b23.x); fma2(acc[2][3], a2, b23.y);
                    fma2(acc[3][0], a3, b01.x); fma2(acc[3][1], a3, b01.y);
                    fma2(acc[3][2], a3, b23.x); fma2(acc[3][3], a3, b23.y);
                }
            }
#pragma unroll
            for (int i = 0; i < 4; ++i) {
                ulonglong2 v0; v0.x = acc[i][0]; v0.y = acc[i][1];
                ulonglong2 v1; v1.x = acc[i][2]; v1.y = acc[i][3];
                *(ulonglong2*)(myPart + (m0 + i) * 128 + n0)     = v0;
                *(ulonglong2*)(myPart + (m0 + i) * 128 + n0 + 4) = v1;
            }

            // ---- group arrive + spin (padded line, R5 semantics) ----
            __threadfence();
            __syncthreads();
            ++myIter;
            if (tid == 0) {
                atomicAdd(&g_grp[grp].v, 1);
                const unsigned tgt = (unsigned)(myIter * Pk);
                while (ldacq(&g_grp[grp].v) < tgt) {}
            }
            __syncthreads();

            // ---- finalize my 1/Pk slice ----
            float* const hT = (layer == 0) ? &g_h0T[s & 1][0]
                                           : &g_h1T[(s & 1) ^ 1][0];
            if (layer == 0)
                finalize_slice<L0_PK>(partBase, out, hT, t, 0, row0, pk, tid);
            else
                finalize_slice<L1_PK>(partBase, out, hT, t, 1, row0, pk, tid);
        }
        grid_barrier(tid);
    }

    // replay-safe reset (past final barrier, R5 semantics)
    if (bid == 0 && tid < 16) g_grp[tid].v = 0;
}

extern "C" void kernel_launch(void* const* d_in, const int* in_sizes, int n_in,
                              void* d_out, int out_size)
{
    const float* x     = (const float*)d_in[0];
    const float* Win0  = (const float*)d_in[1];
    const float* What0 = (const float*)d_in[2];
    const float* Win1  = (const float*)d_in[3];
    const float* What1 = (const float*)d_in[4];
    float* out = (float*)d_out;
    (void)in_sizes; (void)n_in; (void)out_size;

    transpose_x<<<TT, 256>>>(x);
    cudaFuncSetAttribute(esn_kernel,
                         cudaFuncAttributeMaxDynamicSharedMemorySize, SMEM_BYTES);
    esn_kernel<<<NBLK, NTHR, SMEM_BYTES>>>(Win0, What0, Win1, What1, out);
}